// round 11
// baseline (speedup 1.0000x reference)
#include <cuda_runtime.h>
#include <cuda_bf16.h>
#include <math.h>
#include <stdint.h>

#define Bsz 8192
#define Knod 16
#define Eedg 64
#define FIN 300
#define FOUT 64
#define ALPHA 1.0f
#define BETA 0.6f

static __device__ float g_Y[(size_t)3 * Bsz * Knod * FOUT];   // ~100 MB scratch
static __device__ uint4 g_Wfrag[4864];     // encoder B frags: hi [0,2432), lo [2432,4864)
static __device__ uint4 g_WdF[4864];       // decoder B frags: hi [0,2432), lo [2432,4864)
static __device__ float g_V[(size_t)2 * Bsz * FOUT];          // decoder inputs, row = 2b+dec
static __device__ float g_nd[2 * Bsz];
static __device__ float g_lt1[Bsz];
static __device__ float g_lt2[Bsz];
static __device__ float g_contr[Bsz];
static __device__ float g_part[256 * 4];

// ---------------- helpers ----------------
__device__ __forceinline__ uint32_t pk_bf2(float x, float y) {
    __nv_bfloat162 t = __floats2bfloat162_rn(x, y);   // x in low 16 bits
    return *(uint32_t*)&t;
}
__device__ __forceinline__ float low_bf(uint32_t h)  { return __uint_as_float(h << 16); }
__device__ __forceinline__ float high_bf(uint32_t h) { return __uint_as_float(h & 0xffff0000u); }

__device__ __forceinline__ void mma16816(float* c, uint32_t a0, uint32_t a1, uint32_t a2, uint32_t a3,
                                         uint32_t b0, uint32_t b1) {
    asm volatile(
        "mma.sync.aligned.m16n8k16.row.col.f32.bf16.bf16.f32 "
        "{%0,%1,%2,%3}, {%4,%5,%6,%7}, {%8,%9}, {%0,%1,%2,%3};"
        : "+f"(c[0]), "+f"(c[1]), "+f"(c[2]), "+f"(c[3])
        : "r"(a0), "r"(a1), "r"(a2), "r"(a3), "r"(b0), "r"(b1));
}
__device__ __forceinline__ float wred(float v) {
    v += __shfl_xor_sync(0xffffffffu, v, 16);
    v += __shfl_xor_sync(0xffffffffu, v, 8);
    v += __shfl_xor_sync(0xffffffffu, v, 4);
    v += __shfl_xor_sync(0xffffffffu, v, 2);
    v += __shfl_xor_sync(0xffffffffu, v, 1);
    return v;
}
__device__ __forceinline__ float bsum256(float v, float* sR) {
    int tid = threadIdx.x;
    sR[tid] = v;
    __syncthreads();
#pragma unroll
    for (int s = 128; s > 0; s >>= 1) {
        if (tid < s) sR[tid] += sR[tid + s];
        __syncthreads();
    }
    float r = sR[0];
    __syncthreads();
    return r;
}
__device__ __forceinline__ float bsum128(float v, float* sR) {
    int tid = threadIdx.x;
    sR[tid] = v;
    __syncthreads();
#pragma unroll
    for (int s = 64; s > 0; s >>= 1) {
        if (tid < s) sR[tid] += sR[tid + s];
        __syncthreads();
    }
    float r = sR[0];
    __syncthreads();
    return r;
}

// ===========================================================================
// Kernel 0: precompute W_enc + W_dec fragments (bf16 hi/lo, HMMA B layout)
// ===========================================================================
__global__ void prep_W(const float* __restrict__ W_enc, const float* __restrict__ W_dec) {
    int idx = blockIdx.x * blockDim.x + threadIdx.x;
    if (idx < 4864) {
        int lane = idx & 31, nt = (idx >> 5) & 7, kt = idx >> 8;
        int tig = lane & 3, grp = lane >> 2;
        int n = nt * 8 + grp;
        int k0 = kt * 16 + 2 * tig;
        float e0 = __ldg(&W_enc[k0 * 64 + n]);
        float e1 = __ldg(&W_enc[(k0 + 1) * 64 + n]);
        float e2 = (k0 + 8 < FIN) ? __ldg(&W_enc[(k0 + 8) * 64 + n]) : 0.f;
        float e3 = (k0 + 9 < FIN) ? __ldg(&W_enc[(k0 + 9) * 64 + n]) : 0.f;
        uint32_t b0h = pk_bf2(e0, e1), b1h = pk_bf2(e2, e3);
        uint32_t b0l = pk_bf2(e0 - low_bf(b0h), e1 - high_bf(b0h));
        uint32_t b1l = pk_bf2(e2 - low_bf(b1h), e3 - high_bf(b1h));
        uint32_t* gw = (uint32_t*)g_Wfrag;
        int base = (((kt * 4) + (nt >> 1)) * 32 + lane) * 4 + (nt & 1) * 2;
        gw[base] = b0h;  gw[base + 1] = b1h;
        gw[9728 + base] = b0l;  gw[9728 + base + 1] = b1l;
    } else {
        int i2 = idx - 4864;
        if (i2 >= 4864) return;
        int lane = i2 & 31, kt = (i2 >> 5) & 3, nt = i2 >> 7;
        int tig = lane & 3, grp = lane >> 2;
        int n = nt * 8 + grp;
        int k0 = kt * 16 + 2 * tig;
        float e0 = 0.f, e1 = 0.f, e2 = 0.f, e3 = 0.f;
        if (n < FIN) {
            e0 = __ldg(&W_dec[k0 * FIN + n]);
            e1 = __ldg(&W_dec[(k0 + 1) * FIN + n]);
            e2 = __ldg(&W_dec[(k0 + 8) * FIN + n]);
            e3 = __ldg(&W_dec[(k0 + 9) * FIN + n]);
        }
        uint32_t b0h = pk_bf2(e0, e1), b1h = pk_bf2(e2, e3);
        uint32_t b0l = pk_bf2(e0 - low_bf(b0h), e1 - high_bf(b0h));
        uint32_t b1l = pk_bf2(e2 - low_bf(b1h), e3 - high_bf(b1h));
        uint32_t* gw = (uint32_t*)g_WdF;
        int base = (((nt >> 1) * 4 + kt) * 32 + lane) * 4 + (nt & 1) * 2;
        gw[base] = b0h;  gw[base + 1] = b1h;
        gw[9728 + base] = b0l;  gw[9728 + base + 1] = b1l;
    }
}

// ===========================================================================
// Kernel 1: HMMA split-bf16 GEMM  Y = feat @ W_enc  (depth-2 prefetch)
// ===========================================================================
#define GEMM_SMEM (4864 * 16)

__global__ void __launch_bounds__(256, 2) gemm_mma(
    const float* __restrict__ f1, const float* __restrict__ f2,
    const float* __restrict__ fn)
{
    extern __shared__ uint4 sB[];    // hi [0,2432), lo [2432,4864)
    const int tid = threadIdx.x;
    const int w = tid >> 5, lane = tid & 31;
    const int grp = lane >> 2, tig = lane & 3;

#pragma unroll
    for (int u = 0; u < 19; u++) sB[tid + 256 * u] = g_Wfrag[tid + 256 * u];
    __syncthreads();

    const int s = blockIdx.x >> 10, blk = blockIdx.x & 1023;
    const float* A = ((s == 0) ? f1 : (s == 1) ? f2 : fn) + (size_t)blk * 128 * FIN;
    const float* Ar0 = A + (size_t)(w * 16 + grp) * FIN;
    const float* Ar1 = Ar0 + 8 * FIN;

    float acc[8][4];
#pragma unroll
    for (int nt = 0; nt < 8; nt++)
#pragma unroll
        for (int q = 0; q < 4; q++) acc[nt][q] = 0.f;

    // depth-2 prefetch pipeline
    float2 v00, v10, v01, v11;     // kt
    float2 t00, t10, t01, t11;     // kt+1
    {
        const int c0 = 2 * tig;
        v00 = *(const float2*)(Ar0 + c0);
        v10 = *(const float2*)(Ar1 + c0);
        v01 = *(const float2*)(Ar0 + c0 + 8);
        v11 = *(const float2*)(Ar1 + c0 + 8);
        const int d0 = 16 + 2 * tig;
        t00 = *(const float2*)(Ar0 + d0);
        t10 = *(const float2*)(Ar1 + d0);
        t01 = *(const float2*)(Ar0 + d0 + 8);
        t11 = *(const float2*)(Ar1 + d0 + 8);
    }

#pragma unroll 1
    for (int kt = 0; kt < 19; kt++) {
        // issue loads for kt+2 first (in flight under this kt's MMAs)
        float2 u00, u10, u01, u11;
        if (kt < 17) {
            const int c0 = (kt + 2) * 16 + 2 * tig;
            const int c1 = c0 + 8;
            u00 = *(const float2*)(Ar0 + c0);
            u10 = *(const float2*)(Ar1 + c0);
            u01 = (c1 < FIN) ? *(const float2*)(Ar0 + c1) : make_float2(0.f, 0.f);
            u11 = (c1 < FIN) ? *(const float2*)(Ar1 + c1) : make_float2(0.f, 0.f);
        } else {
            u00 = u10 = u01 = u11 = make_float2(0.f, 0.f);
        }

        uint32_t ah0 = pk_bf2(v00.x, v00.y);
        uint32_t ah1 = pk_bf2(v10.x, v10.y);
        uint32_t ah2 = pk_bf2(v01.x, v01.y);
        uint32_t ah3 = pk_bf2(v11.x, v11.y);
        uint32_t al0 = pk_bf2(v00.x - low_bf(ah0), v00.y - high_bf(ah0));
        uint32_t al1 = pk_bf2(v10.x - low_bf(ah1), v10.y - high_bf(ah1));
        uint32_t al2 = pk_bf2(v01.x - low_bf(ah2), v01.y - high_bf(ah2));
        uint32_t al3 = pk_bf2(v11.x - low_bf(ah3), v11.y - high_bf(ah3));

#pragma unroll
        for (int p = 0; p < 4; p++) {
            uint4 H = sB[(kt * 4 + p) * 32 + lane];
            uint4 L = sB[2432 + (kt * 4 + p) * 32 + lane];
            mma16816(acc[2 * p],     ah0, ah1, ah2, ah3, H.x, H.y);
            mma16816(acc[2 * p + 1], ah0, ah1, ah2, ah3, H.z, H.w);
            mma16816(acc[2 * p],     ah0, ah1, ah2, ah3, L.x, L.y);
            mma16816(acc[2 * p + 1], ah0, ah1, ah2, ah3, L.z, L.w);
            mma16816(acc[2 * p],     al0, al1, al2, al3, H.x, H.y);
            mma16816(acc[2 * p + 1], al0, al1, al2, al3, H.z, H.w);
        }
        v00 = t00; v10 = t10; v01 = t01; v11 = t11;
        t00 = u00; t10 = u10; t01 = u01; t11 = u11;
    }

    float* Yb = g_Y + ((size_t)s * (Bsz * Knod) + (size_t)blk * 128 + w * 16) * 64;
#pragma unroll
    for (int nt = 0; nt < 8; nt++) {
        int col = nt * 8 + 2 * tig;
        *(float2*)(Yb + (size_t)grp * 64 + col)       = make_float2(acc[nt][0], acc[nt][1]);
        *(float2*)(Yb + (size_t)(grp + 8) * 64 + col) = make_float2(acc[nt][2], acc[nt][3]);
    }
}

// ===========================================================================
// Kernel 2: warp-per-graph encoder/SpMM/disc pipeline.
// ===========================================================================
#define GSTR 2752
#define OY    0
#define OAGG  1024
#define OSRC  2048
#define ODST  2112
#define OWE   2176
#define OA    2240
#define OPOOL 2368
#define OSCAL 2688
#define ODEG  2696
#define GK_SMEM ((8 * GSTR + 64 * 65) * 4)

__global__ void __launch_bounds__(256, 2) graph_kernel(
    const float* __restrict__ w_p1, const float* __restrict__ w_p2,
    const float* __restrict__ w_n,
    const float* __restrict__ b_enc, const float* __restrict__ W_bil,
    const float* __restrict__ b_bil,
    const int* __restrict__ sp1, const int* __restrict__ dp1,
    const int* __restrict__ sp2, const int* __restrict__ dp2,
    const int* __restrict__ spn, const int* __restrict__ dpn)
{
    extern __shared__ float sm[];
    float* sWb = sm + 8 * GSTR;
    const int tid = threadIdx.x, lane = tid & 31, g = tid >> 5;
    const int b = blockIdx.x * 8 + g;
    float* G = sm + g * GSTR;
    int* Gsrc = (int*)(G + OSRC);
    int* Gdst = (int*)(G + ODST);
    float* Gwe = G + OWE;

    for (int j = tid; j < 4096; j += 256)
        sWb[(j >> 6) * 65 + (j & 63)] = __ldg(&W_bil[j]);
    __syncthreads();

    const float2 be = *(const float2*)&b_enc[2 * lane];

    const int* srcs[3] = { sp1 + (long)b * Eedg, sp2 + (long)b * Eedg, spn + (long)b * Eedg };
    const int* dsts[3] = { dp1 + (long)b * Eedg, dp2 + (long)b * Eedg, dpn + (long)b * Eedg };
    const float* wgts[3] = { w_p1 + (long)b * Eedg, w_p2 + (long)b * Eedg, w_n + (long)b * Eedg };

    for (int s = 0; s < 3; s++) {
        Gsrc[lane] = __ldg(&srcs[s][lane]);  Gsrc[lane + 32] = __ldg(&srcs[s][lane + 32]);
        Gdst[lane] = __ldg(&dsts[s][lane]);  Gdst[lane + 32] = __ldg(&dsts[s][lane + 32]);
        Gwe[lane]  = __ldg(&wgts[s][lane]);  Gwe[lane + 32]  = __ldg(&wgts[s][lane + 32]);
        const float4* Yf4 = (const float4*)(g_Y + ((size_t)s * (Bsz * Knod) + (size_t)b * Knod) * 64);
#pragma unroll
        for (int u = 0; u < 8; u++)
            *(float4*)&G[OY + 4 * (lane + 32 * u)] = __ldg(&Yf4[lane + 32 * u]);
#pragma unroll
        for (int k = 0; k < Knod; k++)
            *(float2*)&G[OAGG + k * 64 + 2 * lane] = make_float2(0.f, 0.f);
        __syncwarp();

        for (int e = 0; e < Eedg; e++) {
            int se = Gsrc[e];
            if (se != 0) {
                int de = Gdst[e]; float w = Gwe[e];
                float2 y = *(const float2*)&G[OY + se * 64 + 2 * lane];
                float2* ap = (float2*)&G[OAGG + de * 64 + 2 * lane];
                float2 a = *ap;
                a.x = fmaf(w, y.x, a.x); a.y = fmaf(w, y.y, a.y);
                *ap = a;
            }
        }

        float px = 0.f, py = 0.f;
        if (s < 2) {
            float2 h2[Knod];
            float ssq[Knod];
#pragma unroll
            for (int k = 0; k < Knod; k++) {
                float2 v = *(const float2*)&G[OAGG + k * 64 + 2 * lane];
                v.x = fmaxf(v.x + be.x, 0.f); v.y = fmaxf(v.y + be.y, 0.f);
                px += v.x; py += v.y;
                h2[k] = v;
                ssq[k] = v.x * v.x + v.y * v.y;
            }
#pragma unroll
            for (int st = 16; st > 0; st >>= 1)
#pragma unroll
                for (int k = 0; k < Knod; k++)
                    ssq[k] += __shfl_xor_sync(0xffffffffu, ssq[k], st);
#pragma unroll
            for (int k = 0; k < Knod; k++) {
                float inv = 1.f / fmaxf(sqrtf(ssq[k]), 1e-12f);
                float2 v = h2[k];
                v.x *= inv; v.y *= inv;
                *(float2*)&G[OAGG + k * 64 + 2 * lane] = v;
            }
        } else {
#pragma unroll
            for (int k = 0; k < Knod; k++) {
                float2 v = *(const float2*)&G[OAGG + k * 64 + 2 * lane];
                px += fmaxf(v.x + be.x, 0.f);
                py += fmaxf(v.y + be.y, 0.f);
            }
        }
        px *= (1.f / 16.f); py *= (1.f / 16.f);
        float pn = wred(px * px + py * py);
        float pinv = 1.f / fmaxf(sqrtf(pn), 1e-12f);
        G[OPOOL + s * 64 + 2 * lane]     = px * pinv;
        G[OPOOL + s * 64 + 2 * lane + 1] = py * pinv;

        if (s < 2) {
            float2 av = *(const float2*)&G[OY + 2 * lane];
            av.x = fmaxf(av.x + be.x, 0.f); av.y = fmaxf(av.y + be.y, 0.f);
            float an = wred(av.x * av.x + av.y * av.y);
            float ainv = 1.f / fmaxf(sqrtf(an), 1e-12f);
            G[OA + s * 64 + 2 * lane]     = av.x * ainv;
            G[OA + s * 64 + 2 * lane + 1] = av.y * ainv;

            {
                const int target = lane & 15;
                const int* arr = (lane < 16) ? Gsrc : Gdst;
                int c = 0;
                for (int e = 0; e < Eedg; e++) c += (arr[e] == target);
                if (lane < 16) G[ODEG + lane] = (float)c;
                if (lane == 16) g_nd[2 * b + s] = rsqrtf(fmaxf((float)c, 1.f));
            }
            __syncwarp();

            float vx = 0.f, vy = 0.f;
            for (int e = 0; e < Eedg; e++) {
                if (Gdst[e] == 0) {
                    int se = Gsrc[e];
                    float rs = rsqrtf(fmaxf(G[ODEG + se], 1.f)) * Gwe[e];
                    float2 h2v = *(const float2*)&G[OAGG + se * 64 + 2 * lane];
                    vx = fmaf(rs, h2v.x, vx);
                    vy = fmaf(rs, h2v.y, vy);
                }
            }
            *(float2*)&g_V[(size_t)(2 * b + s) * 64 + 2 * lane] = make_float2(vx, vy);
        }
        __syncwarp();
    }

    // discriminators
    {
        const float bb = __ldg(b_bil);
        for (int t = 0; t < 2; t++) {
            float u0 = 0.f, u1 = 0.f;
            const float* wr0 = sWb + lane * 65;
            const float* wr1 = sWb + (lane + 32) * 65;
#pragma unroll 8
            for (int k = 0; k < 64; k++) {
                float ak = G[OA + t * 64 + k];
                u0 = fmaf(wr0[k], ak, u0);
                u1 = fmaf(wr1[k], ak, u1);
            }
            float dp = wred(G[OPOOL + t * 64 + lane] * u0 + G[OPOOL + t * 64 + lane + 32] * u1);
            float dn = wred(G[OPOOL + 128 + lane] * u0 + G[OPOOL + 128 + lane + 32] * u1);
            if (lane == 0) {
                G[OSCAL + t]     = 1.f / (1.f + expf(-(dp + bb)));
                G[OSCAL + 2 + t] = 1.f / (1.f + expf(-(dn + bb)));
            }
        }
    }
    __syncwarp();

    if (lane == 0) {
        float ps1 = G[OSCAL + 0], ps2 = G[OSCAL + 1];
        float ns1 = G[OSCAL + 2], ns2 = G[OSCAL + 3];
        g_lt1[b] = logf(ps1) + logf(1.f - ns1);
        g_lt2[b] = logf(ps2) + logf(1.f - ns2);
        g_contr[b] = (ns1 - ps1 + 1.f) * 0.5f + (ns2 - ps2 + 1.f) * 0.5f;
    }
}

// ===========================================================================
// Kernel 3: HMMA decoder + fused error. 256 CTAs x 128 thr; warp = 16 rows.
// 4 independent MMA chains per ntp; e = ssq*inv^2 - 2*inv*dot + osq.
// ===========================================================================
__global__ void __launch_bounds__(128) dec_err(
    const float* __restrict__ fp1, const float* __restrict__ fp2,
    const float* __restrict__ b_dec)
{
    __shared__ float sErow[64];
    __shared__ float sR[128];
    const int tid = threadIdx.x;
    const int w = tid >> 5, lane = tid & 31;
    const int grp = lane >> 2, tig = lane & 3;
    const int base = blockIdx.x * 64 + w * 16;
    const int r0 = base + grp, r1 = r0 + 8;

    // A fragments from V rows (split bf16)
    uint32_t ah[4][4], al[4][4];
#pragma unroll
    for (int kt = 0; kt < 4; kt++) {
        const int k0 = kt * 16 + 2 * tig;
        float2 x00 = *(const float2*)&g_V[(size_t)r0 * 64 + k0];
        float2 x10 = *(const float2*)&g_V[(size_t)r1 * 64 + k0];
        float2 x01 = *(const float2*)&g_V[(size_t)r0 * 64 + k0 + 8];
        float2 x11 = *(const float2*)&g_V[(size_t)r1 * 64 + k0 + 8];
        ah[kt][0] = pk_bf2(x00.x, x00.y);
        ah[kt][1] = pk_bf2(x10.x, x10.y);
        ah[kt][2] = pk_bf2(x01.x, x01.y);
        ah[kt][3] = pk_bf2(x11.x, x11.y);
        al[kt][0] = pk_bf2(x00.x - low_bf(ah[kt][0]), x00.y - high_bf(ah[kt][0]));
        al[kt][1] = pk_bf2(x10.x - low_bf(ah[kt][1]), x10.y - high_bf(ah[kt][1]));
        al[kt][2] = pk_bf2(x01.x - low_bf(ah[kt][2]), x01.y - high_bf(ah[kt][2]));
        al[kt][3] = pk_bf2(x11.x - low_bf(ah[kt][3]), x11.y - high_bf(ah[kt][3]));
    }
    const float nd0 = g_nd[r0], nd1 = g_nd[r1];
    const float* ori0 = ((r0 & 1) ? fp2 : fp1) + (size_t)(r0 >> 1) * (Knod * FIN);
    const float* ori1 = ((r1 & 1) ? fp2 : fp1) + (size_t)(r1 >> 1) * (Knod * FIN);

    float shh0 = 0.f, sho0 = 0.f, soo0 = 0.f;
    float shh1 = 0.f, sho1 = 0.f, soo1 = 0.f;

#pragma unroll 1
    for (int ntp = 0; ntp < 19; ntp++) {
        // 4 independent accumulation chains: (A/B kt halves) x (n half)
        float a0A[4] = {0.f, 0.f, 0.f, 0.f}, a0B[4] = {0.f, 0.f, 0.f, 0.f};
        float a1A[4] = {0.f, 0.f, 0.f, 0.f}, a1B[4] = {0.f, 0.f, 0.f, 0.f};
#pragma unroll
        for (int kh = 0; kh < 2; kh++) {
#pragma unroll
            for (int kq = 0; kq < 2; kq++) {
                const int kt = kh * 2 + kq;
                float* c0 = kh ? a0B : a0A;
                float* c1 = kh ? a1B : a1A;
                uint4 H = __ldg(&g_WdF[(ntp * 4 + kt) * 32 + lane]);
                uint4 L = __ldg(&g_WdF[2432 + (ntp * 4 + kt) * 32 + lane]);
                mma16816(c0, ah[kt][0], ah[kt][1], ah[kt][2], ah[kt][3], H.x, H.y);
                mma16816(c1, ah[kt][0], ah[kt][1], ah[kt][2], ah[kt][3], H.z, H.w);
                mma16816(c0, ah[kt][0], ah[kt][1], ah[kt][2], ah[kt][3], L.x, L.y);
                mma16816(c1, ah[kt][0], ah[kt][1], ah[kt][2], ah[kt][3], L.z, L.w);
                mma16816(c0, al[kt][0], al[kt][1], al[kt][2], al[kt][3], H.x, H.y);
                mma16816(c1, al[kt][0], al[kt][1], al[kt][2], al[kt][3], H.z, H.w);
            }
        }
        float acc0[4], acc1[4];
#pragma unroll
        for (int q = 0; q < 4; q++) { acc0[q] = a0A[q] + a0B[q]; acc1[q] = a1A[q] + a1B[q]; }

#pragma unroll
        for (int half = 0; half < 2; half++) {
            const float* accP = half ? acc1 : acc0;
            const int col = ntp * 16 + half * 8 + 2 * tig;
            if (col < FIN) {
                float2 bd = *(const float2*)&b_dec[col];
                float h00 = fmaxf(accP[0] * nd0 + bd.x, 0.f);
                float h01 = fmaxf(accP[1] * nd0 + bd.y, 0.f);
                float h10 = fmaxf(accP[2] * nd1 + bd.x, 0.f);
                float h11 = fmaxf(accP[3] * nd1 + bd.y, 0.f);
                float2 o0 = *(const float2*)(ori0 + col);
                float2 o1 = *(const float2*)(ori1 + col);
                shh0 += h00 * h00 + h01 * h01;
                sho0 += h00 * o0.x + h01 * o0.y;
                soo0 += o0.x * o0.x + o0.y * o0.y;
                shh1 += h10 * h10 + h11 * h11;
                sho1 += h10 * o1.x + h11 * o1.y;
                soo1 += o1.x * o1.x + o1.y * o1.y;
            }
        }
    }

#pragma unroll
    for (int st = 1; st < 4; st <<= 1) {
        shh0 += __shfl_xor_sync(0xffffffffu, shh0, st);
        sho0 += __shfl_xor_sync(0xffffffffu, sho0, st);
        soo0 += __shfl_xor_sync(0xffffffffu, soo0, st);
        shh1 += __shfl_xor_sync(0xffffffffu, shh1, st);
        sho1 += __shfl_xor_sync(0xffffffffu, sho1, st);
        soo1 += __shfl_xor_sync(0xffffffffu, soo1, st);
    }
    if (tig == 0) {
        float inv0 = 1.f / fmaxf(sqrtf(shh0), 1e-12f);
        float inv1 = 1.f / fmaxf(sqrtf(shh1), 1e-12f);
        sErow[w * 16 + grp]     = shh0 * inv0 * inv0 - 2.f * inv0 * sho0 + soo0;
        sErow[w * 16 + grp + 8] = shh1 * inv1 * inv1 - 2.f * inv1 * sho1 + soo1;
    }
    __syncthreads();

    // CTA partials over this CTA's 32 graphs (64 rows)
    float vE0 = 0.f, vE1 = 0.f;
    if (tid < 64) {
        float e = sErow[tid];
        if ((tid & 1) == 0) vE0 = e; else vE1 = e;
    }
    const int gb = blockIdx.x * 32;
    float E0 = bsum128(vE0, sR);
    float E1 = bsum128(vE1, sR);
    float L1 = bsum128((tid < 32) ? g_lt1[gb + tid] : 0.f, sR);
    float L2 = bsum128((tid < 32) ? g_lt2[gb + tid] : 0.f, sR);
    if (tid == 0) {
        g_part[blockIdx.x * 4 + 0] = E0;
        g_part[blockIdx.x * 4 + 1] = E1;
        g_part[blockIdx.x * 4 + 2] = L1;
        g_part[blockIdx.x * 4 + 3] = L2;
    }
}

// ===========================================================================
// Kernel 4: fused finalize + scores. 32 CTAs x 256; each CTA redundantly
// reduces the 256x4 partials (1 KB), CTA 0 writes L, all write score slices.
// ===========================================================================
__global__ void __launch_bounds__(256) fin_scores(float* out) {
    __shared__ float sR[256];
    const int tid = threadIdx.x;
    float a  = g_part[tid * 4 + 0];
    float c  = g_part[tid * 4 + 1];
    float m1 = g_part[tid * 4 + 2];
    float m2 = g_part[tid * 4 + 3];
    float Ssq1 = bsum256(a, sR);
    float Ssq2 = bsum256(c, sR);
    float M1 = bsum256(m1, sR);
    float M2 = bsum256(m2, sR);

    if (blockIdx.x == 0 && tid == 0) {
        float L_con = -(M1 / (float)Bsz + M2 / (float)Bsz) * 0.25f;
        float L_gen = (Ssq1 + Ssq2) / (2.f * (float)Bsz * (float)FIN);
        out[0] = ALPHA * L_con + BETA * L_gen;
    }
    float gen = (sqrtf(Ssq1) + sqrtf(Ssq2)) / (2.f * sqrtf((float)FIN));
    int i = blockIdx.x * 256 + tid;
    out[1 + i] = ALPHA * g_contr[i] + BETA * gen;
}

// ===========================================================================
extern "C" void kernel_launch(void* const* d_in, const int* in_sizes, int n_in,
                              void* d_out, int out_size) {
    const float* feat_p1 = (const float*)d_in[0];
    const float* feat_p2 = (const float*)d_in[1];
    const float* feat_n  = (const float*)d_in[2];
    const float* w_p1    = (const float*)d_in[3];
    const float* w_p2    = (const float*)d_in[4];
    const float* w_n     = (const float*)d_in[5];
    const float* W_enc   = (const float*)d_in[6];
    const float* b_enc   = (const float*)d_in[7];
    const float* W_dec   = (const float*)d_in[8];
    const float* b_dec   = (const float*)d_in[9];
    const float* W_bil   = (const float*)d_in[10];
    const float* b_bil   = (const float*)d_in[11];
    const int* src_p1 = (const int*)d_in[12];
    const int* dst_p1 = (const int*)d_in[13];
    const int* src_p2 = (const int*)d_in[14];
    const int* dst_p2 = (const int*)d_in[15];
    const int* src_n  = (const int*)d_in[16];
    const int* dst_n  = (const int*)d_in[17];
    float* out = (float*)d_out;

    cudaFuncSetAttribute(gemm_mma, cudaFuncAttributeMaxDynamicSharedMemorySize, GEMM_SMEM);
    cudaFuncSetAttribute(graph_kernel, cudaFuncAttributeMaxDynamicSharedMemorySize, GK_SMEM);

    prep_W<<<38, 256>>>(W_enc, W_dec);
    gemm_mma<<<3072, 256, GEMM_SMEM>>>(feat_p1, feat_p2, feat_n);

    graph_kernel<<<Bsz / 8, 256, GK_SMEM>>>(
        w_p1, w_p2, w_n, b_enc, W_bil, b_bil,
        src_p1, dst_p1, src_p2, dst_p2, src_n, dst_n);

    dec_err<<<256, 128>>>(feat_p1, feat_p2, b_dec);
    fin_scores<<<32, 256>>>(out);
}

// round 15
// speedup vs baseline: 1.3621x; 1.3621x over previous
#include <cuda_runtime.h>
#include <cuda_bf16.h>
#include <math.h>
#include <stdint.h>

#define Bsz 8192
#define Knod 16
#define Eedg 64
#define FIN 300
#define FOUT 64
#define ALPHA 1.0f
#define BETA 0.6f

static __device__ float g_Y[(size_t)3 * Bsz * Knod * FOUT];   // ~100 MB scratch
static __device__ uint4 g_Wfrag[4864];     // encoder B frags: hi [0,2432), lo [2432,4864)
static __device__ uint4 g_WdF[4864];       // decoder B frags: hi [0,2432), lo [2432,4864)
static __device__ float g_V[(size_t)2 * Bsz * FOUT];          // decoder inputs, row = 2b+dec
static __device__ float g_nd[2 * Bsz];
static __device__ float g_lt1[Bsz];
static __device__ float g_lt2[Bsz];
static __device__ float g_contr[Bsz];
static __device__ float g_part[256 * 4];

// ---------------- helpers ----------------
__device__ __forceinline__ uint32_t pk_bf2(float x, float y) {
    __nv_bfloat162 t = __floats2bfloat162_rn(x, y);   // x in low 16 bits
    return *(uint32_t*)&t;
}
__device__ __forceinline__ float low_bf(uint32_t h)  { return __uint_as_float(h << 16); }
__device__ __forceinline__ float high_bf(uint32_t h) { return __uint_as_float(h & 0xffff0000u); }

__device__ __forceinline__ void mma16816(float* c, uint32_t a0, uint32_t a1, uint32_t a2, uint32_t a3,
                                         uint32_t b0, uint32_t b1) {
    asm volatile(
        "mma.sync.aligned.m16n8k16.row.col.f32.bf16.bf16.f32 "
        "{%0,%1,%2,%3}, {%4,%5,%6,%7}, {%8,%9}, {%0,%1,%2,%3};"
        : "+f"(c[0]), "+f"(c[1]), "+f"(c[2]), "+f"(c[3])
        : "r"(a0), "r"(a1), "r"(a2), "r"(a3), "r"(b0), "r"(b1));
}
__device__ __forceinline__ float wred(float v) {
    v += __shfl_xor_sync(0xffffffffu, v, 16);
    v += __shfl_xor_sync(0xffffffffu, v, 8);
    v += __shfl_xor_sync(0xffffffffu, v, 4);
    v += __shfl_xor_sync(0xffffffffu, v, 2);
    v += __shfl_xor_sync(0xffffffffu, v, 1);
    return v;
}
__device__ __forceinline__ float bsum256(float v, float* sR) {
    int tid = threadIdx.x;
    sR[tid] = v;
    __syncthreads();
#pragma unroll
    for (int s = 128; s > 0; s >>= 1) {
        if (tid < s) sR[tid] += sR[tid + s];
        __syncthreads();
    }
    float r = sR[0];
    __syncthreads();
    return r;
}
__device__ __forceinline__ float bsum128(float v, float* sR) {
    int tid = threadIdx.x;
    sR[tid] = v;
    __syncthreads();
#pragma unroll
    for (int s = 64; s > 0; s >>= 1) {
        if (tid < s) sR[tid] += sR[tid + s];
        __syncthreads();
    }
    float r = sR[0];
    __syncthreads();
    return r;
}

// ===========================================================================
// Kernel 0: precompute W_enc + W_dec fragments (bf16 hi/lo, HMMA B layout)
// ===========================================================================
__global__ void prep_W(const float* __restrict__ W_enc, const float* __restrict__ W_dec) {
    int idx = blockIdx.x * blockDim.x + threadIdx.x;
    if (idx < 4864) {
        int lane = idx & 31, nt = (idx >> 5) & 7, kt = idx >> 8;
        int tig = lane & 3, grp = lane >> 2;
        int n = nt * 8 + grp;
        int k0 = kt * 16 + 2 * tig;
        float e0 = __ldg(&W_enc[k0 * 64 + n]);
        float e1 = __ldg(&W_enc[(k0 + 1) * 64 + n]);
        float e2 = (k0 + 8 < FIN) ? __ldg(&W_enc[(k0 + 8) * 64 + n]) : 0.f;
        float e3 = (k0 + 9 < FIN) ? __ldg(&W_enc[(k0 + 9) * 64 + n]) : 0.f;
        uint32_t b0h = pk_bf2(e0, e1), b1h = pk_bf2(e2, e3);
        uint32_t b0l = pk_bf2(e0 - low_bf(b0h), e1 - high_bf(b0h));
        uint32_t b1l = pk_bf2(e2 - low_bf(b1h), e3 - high_bf(b1h));
        uint32_t* gw = (uint32_t*)g_Wfrag;
        int base = (((kt * 4) + (nt >> 1)) * 32 + lane) * 4 + (nt & 1) * 2;
        gw[base] = b0h;  gw[base + 1] = b1h;
        gw[9728 + base] = b0l;  gw[9728 + base + 1] = b1l;
    } else {
        int i2 = idx - 4864;
        if (i2 >= 4864) return;
        int lane = i2 & 31, kt = (i2 >> 5) & 3, nt = i2 >> 7;
        int tig = lane & 3, grp = lane >> 2;
        int n = nt * 8 + grp;
        int k0 = kt * 16 + 2 * tig;
        float e0 = 0.f, e1 = 0.f, e2 = 0.f, e3 = 0.f;
        if (n < FIN) {
            e0 = __ldg(&W_dec[k0 * FIN + n]);
            e1 = __ldg(&W_dec[(k0 + 1) * FIN + n]);
            e2 = __ldg(&W_dec[(k0 + 8) * FIN + n]);
            e3 = __ldg(&W_dec[(k0 + 9) * FIN + n]);
        }
        uint32_t b0h = pk_bf2(e0, e1), b1h = pk_bf2(e2, e3);
        uint32_t b0l = pk_bf2(e0 - low_bf(b0h), e1 - high_bf(b0h));
        uint32_t b1l = pk_bf2(e2 - low_bf(b1h), e3 - high_bf(b1h));
        uint32_t* gw = (uint32_t*)g_WdF;
        int base = (((nt >> 1) * 4 + kt) * 32 + lane) * 4 + (nt & 1) * 2;
        gw[base] = b0h;  gw[base + 1] = b1h;
        gw[9728 + base] = b0l;  gw[9728 + base + 1] = b1l;
    }
}

// ===========================================================================
// Kernel 1: HMMA split-bf16 GEMM  Y = feat @ W_enc  (depth-1 prefetch,
// smem-staged coalesced epilogue)
// ===========================================================================
#define GEMM_SMEM (4864 * 16)

__global__ void __launch_bounds__(256, 2) gemm_mma(
    const float* __restrict__ f1, const float* __restrict__ f2,
    const float* __restrict__ fn)
{
    extern __shared__ uint4 sB[];    // hi [0,2432), lo [2432,4864); reused as sY after k-loop
    const int tid = threadIdx.x;
    const int w = tid >> 5, lane = tid & 31;
    const int grp = lane >> 2, tig = lane & 3;

#pragma unroll
    for (int u = 0; u < 19; u++) sB[tid + 256 * u] = g_Wfrag[tid + 256 * u];
    __syncthreads();

    const int s = blockIdx.x >> 10, blk = blockIdx.x & 1023;
    const float* A = ((s == 0) ? f1 : (s == 1) ? f2 : fn) + (size_t)blk * 128 * FIN;
    const float* Ar0 = A + (size_t)(w * 16 + grp) * FIN;
    const float* Ar1 = Ar0 + 8 * FIN;

    float acc[8][4];
#pragma unroll
    for (int nt = 0; nt < 8; nt++)
#pragma unroll
        for (int q = 0; q < 4; q++) acc[nt][q] = 0.f;

    // depth-1 prefetch (R10 known-good)
    float2 v00, v10, v01, v11;
    {
        const int c0 = 2 * tig, c1 = c0 + 8;
        v00 = *(const float2*)(Ar0 + c0);
        v10 = *(const float2*)(Ar1 + c0);
        v01 = *(const float2*)(Ar0 + c1);
        v11 = *(const float2*)(Ar1 + c1);
    }

#pragma unroll 1
    for (int kt = 0; kt < 19; kt++) {
        uint32_t ah0 = pk_bf2(v00.x, v00.y);
        uint32_t ah1 = pk_bf2(v10.x, v10.y);
        uint32_t ah2 = pk_bf2(v01.x, v01.y);
        uint32_t ah3 = pk_bf2(v11.x, v11.y);
        uint32_t al0 = pk_bf2(v00.x - low_bf(ah0), v00.y - high_bf(ah0));
        uint32_t al1 = pk_bf2(v10.x - low_bf(ah1), v10.y - high_bf(ah1));
        uint32_t al2 = pk_bf2(v01.x - low_bf(ah2), v01.y - high_bf(ah2));
        uint32_t al3 = pk_bf2(v11.x - low_bf(ah3), v11.y - high_bf(ah3));

        // prefetch next k-tile while MMAs run
        float2 t00, t10, t01, t11;
        if (kt < 18) {
            const int c0 = (kt + 1) * 16 + 2 * tig;
            const int c1 = c0 + 8;
            t00 = *(const float2*)(Ar0 + c0);
            t10 = *(const float2*)(Ar1 + c0);
            t01 = (c1 < FIN) ? *(const float2*)(Ar0 + c1) : make_float2(0.f, 0.f);
            t11 = (c1 < FIN) ? *(const float2*)(Ar1 + c1) : make_float2(0.f, 0.f);
        } else {
            t00 = v00; t10 = v10; t01 = v01; t11 = v11;
        }

#pragma unroll
        for (int p = 0; p < 4; p++) {
            uint4 H = sB[(kt * 4 + p) * 32 + lane];
            uint4 L = sB[2432 + (kt * 4 + p) * 32 + lane];
            mma16816(acc[2 * p],     ah0, ah1, ah2, ah3, H.x, H.y);
            mma16816(acc[2 * p + 1], ah0, ah1, ah2, ah3, H.z, H.w);
            mma16816(acc[2 * p],     ah0, ah1, ah2, ah3, L.x, L.y);
            mma16816(acc[2 * p + 1], ah0, ah1, ah2, ah3, L.z, L.w);
            mma16816(acc[2 * p],     al0, al1, al2, al3, H.x, H.y);
            mma16816(acc[2 * p + 1], al0, al1, al2, al3, H.z, H.w);
        }
        v00 = t00; v10 = t10; v01 = t01; v11 = t11;
    }

    // ---- epilogue: stage to smem (sB dead), then coalesced float4 writes ----
    __syncthreads();                      // all warps done reading sB
    float* sY = (float*)sB;               // [128][68] padded rows (34816 B < 77824 B)
#pragma unroll
    for (int nt = 0; nt < 8; nt++) {
        int col = nt * 8 + 2 * tig;
        *(float2*)&sY[(w * 16 + grp) * 68 + col]     = make_float2(acc[nt][0], acc[nt][1]);
        *(float2*)&sY[(w * 16 + grp + 8) * 68 + col] = make_float2(acc[nt][2], acc[nt][3]);
    }
    __syncthreads();
    float* Yc = g_Y + ((size_t)s * (Bsz * Knod) + (size_t)blk * 128) * 64;
#pragma unroll
    for (int u = 0; u < 8; u++) {
        int j = tid + 256 * u;            // 0..2047
        int row = j >> 4, c4 = (j & 15) * 4;
        *(float4*)&Yc[row * 64 + c4] = *(const float4*)&sY[row * 68 + c4];
    }
}

// ===========================================================================
// Kernel 2: warp-per-graph encoder/SpMM/disc pipeline.
// ===========================================================================
#define GSTR 2752
#define OY    0
#define OAGG  1024
#define OSRC  2048
#define ODST  2112
#define OWE   2176
#define OA    2240
#define OPOOL 2368
#define OSCAL 2688
#define ODEG  2696
#define GK_SMEM ((8 * GSTR + 64 * 65) * 4)

__global__ void __launch_bounds__(256, 2) graph_kernel(
    const float* __restrict__ w_p1, const float* __restrict__ w_p2,
    const float* __restrict__ w_n,
    const float* __restrict__ b_enc, const float* __restrict__ W_bil,
    const float* __restrict__ b_bil,
    const int* __restrict__ sp1, const int* __restrict__ dp1,
    const int* __restrict__ sp2, const int* __restrict__ dp2,
    const int* __restrict__ spn, const int* __restrict__ dpn)
{
    extern __shared__ float sm[];
    float* sWb = sm + 8 * GSTR;
    const int tid = threadIdx.x, lane = tid & 31, g = tid >> 5;
    const int b = blockIdx.x * 8 + g;
    float* G = sm + g * GSTR;
    int* Gsrc = (int*)(G + OSRC);
    int* Gdst = (int*)(G + ODST);
    float* Gwe = G + OWE;

    for (int j = tid; j < 4096; j += 256)
        sWb[(j >> 6) * 65 + (j & 63)] = __ldg(&W_bil[j]);
    __syncthreads();

    const float2 be = *(const float2*)&b_enc[2 * lane];

    const int* srcs[3] = { sp1 + (long)b * Eedg, sp2 + (long)b * Eedg, spn + (long)b * Eedg };
    const int* dsts[3] = { dp1 + (long)b * Eedg, dp2 + (long)b * Eedg, dpn + (long)b * Eedg };
    const float* wgts[3] = { w_p1 + (long)b * Eedg, w_p2 + (long)b * Eedg, w_n + (long)b * Eedg };

    for (int s = 0; s < 3; s++) {
        Gsrc[lane] = __ldg(&srcs[s][lane]);  Gsrc[lane + 32] = __ldg(&srcs[s][lane + 32]);
        Gdst[lane] = __ldg(&dsts[s][lane]);  Gdst[lane + 32] = __ldg(&dsts[s][lane + 32]);
        Gwe[lane]  = __ldg(&wgts[s][lane]);  Gwe[lane + 32]  = __ldg(&wgts[s][lane + 32]);
        const float4* Yf4 = (const float4*)(g_Y + ((size_t)s * (Bsz * Knod) + (size_t)b * Knod) * 64);
#pragma unroll
        for (int u = 0; u < 8; u++)
            *(float4*)&G[OY + 4 * (lane + 32 * u)] = __ldg(&Yf4[lane + 32 * u]);
#pragma unroll
        for (int k = 0; k < Knod; k++)
            *(float2*)&G[OAGG + k * 64 + 2 * lane] = make_float2(0.f, 0.f);
        __syncwarp();

        for (int e = 0; e < Eedg; e++) {
            int se = Gsrc[e];
            if (se != 0) {
                int de = Gdst[e]; float w = Gwe[e];
                float2 y = *(const float2*)&G[OY + se * 64 + 2 * lane];
                float2* ap = (float2*)&G[OAGG + de * 64 + 2 * lane];
                float2 a = *ap;
                a.x = fmaf(w, y.x, a.x); a.y = fmaf(w, y.y, a.y);
                *ap = a;
            }
        }

        float px = 0.f, py = 0.f;
        if (s < 2) {
            float2 h2[Knod];
            float ssq[Knod];
#pragma unroll
            for (int k = 0; k < Knod; k++) {
                float2 v = *(const float2*)&G[OAGG + k * 64 + 2 * lane];
                v.x = fmaxf(v.x + be.x, 0.f); v.y = fmaxf(v.y + be.y, 0.f);
                px += v.x; py += v.y;
                h2[k] = v;
                ssq[k] = v.x * v.x + v.y * v.y;
            }
#pragma unroll
            for (int st = 16; st > 0; st >>= 1)
#pragma unroll
                for (int k = 0; k < Knod; k++)
                    ssq[k] += __shfl_xor_sync(0xffffffffu, ssq[k], st);
#pragma unroll
            for (int k = 0; k < Knod; k++) {
                float inv = 1.f / fmaxf(sqrtf(ssq[k]), 1e-12f);
                float2 v = h2[k];
                v.x *= inv; v.y *= inv;
                *(float2*)&G[OAGG + k * 64 + 2 * lane] = v;
            }
        } else {
#pragma unroll
            for (int k = 0; k < Knod; k++) {
                float2 v = *(const float2*)&G[OAGG + k * 64 + 2 * lane];
                px += fmaxf(v.x + be.x, 0.f);
                py += fmaxf(v.y + be.y, 0.f);
            }
        }
        px *= (1.f / 16.f); py *= (1.f / 16.f);
        float pn = wred(px * px + py * py);
        float pinv = 1.f / fmaxf(sqrtf(pn), 1e-12f);
        G[OPOOL + s * 64 + 2 * lane]     = px * pinv;
        G[OPOOL + s * 64 + 2 * lane + 1] = py * pinv;

        if (s < 2) {
            float2 av = *(const float2*)&G[OY + 2 * lane];
            av.x = fmaxf(av.x + be.x, 0.f); av.y = fmaxf(av.y + be.y, 0.f);
            float an = wred(av.x * av.x + av.y * av.y);
            float ainv = 1.f / fmaxf(sqrtf(an), 1e-12f);
            G[OA + s * 64 + 2 * lane]     = av.x * ainv;
            G[OA + s * 64 + 2 * lane + 1] = av.y * ainv;

            {
                const int target = lane & 15;
                const int* arr = (lane < 16) ? Gsrc : Gdst;
                int c = 0;
                for (int e = 0; e < Eedg; e++) c += (arr[e] == target);
                if (lane < 16) G[ODEG + lane] = (float)c;
                if (lane == 16) g_nd[2 * b + s] = rsqrtf(fmaxf((float)c, 1.f));
            }
            __syncwarp();

            float vx = 0.f, vy = 0.f;
            for (int e = 0; e < Eedg; e++) {
                if (Gdst[e] == 0) {
                    int se = Gsrc[e];
                    float rs = rsqrtf(fmaxf(G[ODEG + se], 1.f)) * Gwe[e];
                    float2 h2v = *(const float2*)&G[OAGG + se * 64 + 2 * lane];
                    vx = fmaf(rs, h2v.x, vx);
                    vy = fmaf(rs, h2v.y, vy);
                }
            }
            *(float2*)&g_V[(size_t)(2 * b + s) * 64 + 2 * lane] = make_float2(vx, vy);
        }
        __syncwarp();
    }

    // discriminators
    {
        const float bb = __ldg(b_bil);
        for (int t = 0; t < 2; t++) {
            float u0 = 0.f, u1 = 0.f;
            const float* wr0 = sWb + lane * 65;
            const float* wr1 = sWb + (lane + 32) * 65;
#pragma unroll 8
            for (int k = 0; k < 64; k++) {
                float ak = G[OA + t * 64 + k];
                u0 = fmaf(wr0[k], ak, u0);
                u1 = fmaf(wr1[k], ak, u1);
            }
            float dp = wred(G[OPOOL + t * 64 + lane] * u0 + G[OPOOL + t * 64 + lane + 32] * u1);
            float dn = wred(G[OPOOL + 128 + lane] * u0 + G[OPOOL + 128 + lane + 32] * u1);
            if (lane == 0) {
                G[OSCAL + t]     = 1.f / (1.f + expf(-(dp + bb)));
                G[OSCAL + 2 + t] = 1.f / (1.f + expf(-(dn + bb)));
            }
        }
    }
    __syncwarp();

    if (lane == 0) {
        float ps1 = G[OSCAL + 0], ps2 = G[OSCAL + 1];
        float ns1 = G[OSCAL + 2], ns2 = G[OSCAL + 3];
        g_lt1[b] = logf(ps1) + logf(1.f - ns1);
        g_lt2[b] = logf(ps2) + logf(1.f - ns2);
        g_contr[b] = (ns1 - ps1 + 1.f) * 0.5f + (ns2 - ps2 + 1.f) * 0.5f;
    }
}

// ===========================================================================
// Kernel 3: HMMA decoder + fused error. 256 CTAs x 128 thr; warp = 16 rows.
// e = ssq*inv^2 - 2*inv*dot + osq (hd never materialized).
// ===========================================================================
__global__ void __launch_bounds__(128) dec_err(
    const float* __restrict__ fp1, const float* __restrict__ fp2,
    const float* __restrict__ b_dec)
{
    __shared__ float sErow[64];
    __shared__ float sR[128];
    const int tid = threadIdx.x;
    const int w = tid >> 5, lane = tid & 31;
    const int grp = lane >> 2, tig = lane & 3;
    const int base = blockIdx.x * 64 + w * 16;
    const int r0 = base + grp, r1 = r0 + 8;

    uint32_t ah[4][4], al[4][4];
#pragma unroll
    for (int kt = 0; kt < 4; kt++) {
        const int k0 = kt * 16 + 2 * tig;
        float2 x00 = *(const float2*)&g_V[(size_t)r0 * 64 + k0];
        float2 x10 = *(const float2*)&g_V[(size_t)r1 * 64 + k0];
        float2 x01 = *(const float2*)&g_V[(size_t)r0 * 64 + k0 + 8];
        float2 x11 = *(const float2*)&g_V[(size_t)r1 * 64 + k0 + 8];
        ah[kt][0] = pk_bf2(x00.x, x00.y);
        ah[kt][1] = pk_bf2(x10.x, x10.y);
        ah[kt][2] = pk_bf2(x01.x, x01.y);
        ah[kt][3] = pk_bf2(x11.x, x11.y);
        al[kt][0] = pk_bf2(x00.x - low_bf(ah[kt][0]), x00.y - high_bf(ah[kt][0]));
        al[kt][1] = pk_bf2(x10.x - low_bf(ah[kt][1]), x10.y - high_bf(ah[kt][1]));
        al[kt][2] = pk_bf2(x01.x - low_bf(ah[kt][2]), x01.y - high_bf(ah[kt][2]));
        al[kt][3] = pk_bf2(x11.x - low_bf(ah[kt][3]), x11.y - high_bf(ah[kt][3]));
    }
    const float nd0 = g_nd[r0], nd1 = g_nd[r1];
    const float* ori0 = ((r0 & 1) ? fp2 : fp1) + (size_t)(r0 >> 1) * (Knod * FIN);
    const float* ori1 = ((r1 & 1) ? fp2 : fp1) + (size_t)(r1 >> 1) * (Knod * FIN);

    float shh0 = 0.f, sho0 = 0.f, soo0 = 0.f;
    float shh1 = 0.f, sho1 = 0.f, soo1 = 0.f;

#pragma unroll 1
    for (int ntp = 0; ntp < 19; ntp++) {
        float a0A[4] = {0.f, 0.f, 0.f, 0.f}, a0B[4] = {0.f, 0.f, 0.f, 0.f};
        float a1A[4] = {0.f, 0.f, 0.f, 0.f}, a1B[4] = {0.f, 0.f, 0.f, 0.f};
#pragma unroll
        for (int kh = 0; kh < 2; kh++) {
#pragma unroll
            for (int kq = 0; kq < 2; kq++) {
                const int kt = kh * 2 + kq;
                float* c0 = kh ? a0B : a0A;
                float* c1 = kh ? a1B : a1A;
                uint4 H = __ldg(&g_WdF[(ntp * 4 + kt) * 32 + lane]);
                uint4 L = __ldg(&g_WdF[2432 + (ntp * 4 + kt) * 32 + lane]);
                mma16816(c0, ah[kt][0], ah[kt][1], ah[kt][2], ah[kt][3], H.x, H.y);
                mma16816(c1, ah[kt][0], ah[kt][1], ah[kt][2], ah[kt][3], H.z, H.w);
                mma16816(c0, ah[kt][0], ah[kt][1], ah[kt][2], ah[kt][3], L.x, L.y);
                mma16816(c1, ah[kt][0], ah[kt][1], ah[kt][2], ah[kt][3], L.z, L.w);
                mma16816(c0, al[kt][0], al[kt][1], al[kt][2], al[kt][3], H.x, H.y);
                mma16816(c1, al[kt][0], al[kt][1], al[kt][2], al[kt][3], H.z, H.w);
            }
        }
        float acc0[4], acc1[4];
#pragma unroll
        for (int q = 0; q < 4; q++) { acc0[q] = a0A[q] + a0B[q]; acc1[q] = a1A[q] + a1B[q]; }

#pragma unroll
        for (int half = 0; half < 2; half++) {
            const float* accP = half ? acc1 : acc0;
            const int col = ntp * 16 + half * 8 + 2 * tig;
            if (col < FIN) {
                float2 bd = *(const float2*)&b_dec[col];
                float h00 = fmaxf(accP[0] * nd0 + bd.x, 0.f);
                float h01 = fmaxf(accP[1] * nd0 + bd.y, 0.f);
                float h10 = fmaxf(accP[2] * nd1 + bd.x, 0.f);
                float h11 = fmaxf(accP[3] * nd1 + bd.y, 0.f);
                float2 o0 = *(const float2*)(ori0 + col);
                float2 o1 = *(const float2*)(ori1 + col);
                shh0 += h00 * h00 + h01 * h01;
                sho0 += h00 * o0.x + h01 * o0.y;
                soo0 += o0.x * o0.x + o0.y * o0.y;
                shh1 += h10 * h10 + h11 * h11;
                sho1 += h10 * o1.x + h11 * o1.y;
                soo1 += o1.x * o1.x + o1.y * o1.y;
            }
        }
    }

#pragma unroll
    for (int st = 1; st < 4; st <<= 1) {
        shh0 += __shfl_xor_sync(0xffffffffu, shh0, st);
        sho0 += __shfl_xor_sync(0xffffffffu, sho0, st);
        soo0 += __shfl_xor_sync(0xffffffffu, soo0, st);
        shh1 += __shfl_xor_sync(0xffffffffu, shh1, st);
        sho1 += __shfl_xor_sync(0xffffffffu, sho1, st);
        soo1 += __shfl_xor_sync(0xffffffffu, soo1, st);
    }
    if (tig == 0) {
        float inv0 = 1.f / fmaxf(sqrtf(shh0), 1e-12f);
        float inv1 = 1.f / fmaxf(sqrtf(shh1), 1e-12f);
        sErow[w * 16 + grp]     = shh0 * inv0 * inv0 - 2.f * inv0 * sho0 + soo0;
        sErow[w * 16 + grp + 8] = shh1 * inv1 * inv1 - 2.f * inv1 * sho1 + soo1;
    }
    __syncthreads();

    float vE0 = 0.f, vE1 = 0.f;
    if (tid < 64) {
        float e = sErow[tid];
        if ((tid & 1) == 0) vE0 = e; else vE1 = e;
    }
    const int gb = blockIdx.x * 32;
    float E0 = bsum128(vE0, sR);
    float E1 = bsum128(vE1, sR);
    float L1 = bsum128((tid < 32) ? g_lt1[gb + tid] : 0.f, sR);
    float L2 = bsum128((tid < 32) ? g_lt2[gb + tid] : 0.f, sR);
    if (tid == 0) {
        g_part[blockIdx.x * 4 + 0] = E0;
        g_part[blockIdx.x * 4 + 1] = E1;
        g_part[blockIdx.x * 4 + 2] = L1;
        g_part[blockIdx.x * 4 + 3] = L2;
    }
}

// ===========================================================================
// Kernel 4: fused finalize + scores. 32 CTAs x 256.
// ===========================================================================
__global__ void __launch_bounds__(256) fin_scores(float* out) {
    __shared__ float sR[256];
    const int tid = threadIdx.x;
    float a  = g_part[tid * 4 + 0];
    float c  = g_part[tid * 4 + 1];
    float m1 = g_part[tid * 4 + 2];
    float m2 = g_part[tid * 4 + 3];
    float Ssq1 = bsum256(a, sR);
    float Ssq2 = bsum256(c, sR);
    float M1 = bsum256(m1, sR);
    float M2 = bsum256(m2, sR);

    if (blockIdx.x == 0 && tid == 0) {
        float L_con = -(M1 / (float)Bsz + M2 / (float)Bsz) * 0.25f;
        float L_gen = (Ssq1 + Ssq2) / (2.f * (float)Bsz * (float)FIN);
        out[0] = ALPHA * L_con + BETA * L_gen;
    }
    float gen = (sqrtf(Ssq1) + sqrtf(Ssq2)) / (2.f * sqrtf((float)FIN));
    int i = blockIdx.x * 256 + tid;
    out[1 + i] = ALPHA * g_contr[i] + BETA * gen;
}

// ===========================================================================
extern "C" void kernel_launch(void* const* d_in, const int* in_sizes, int n_in,
                              void* d_out, int out_size) {
    const float* feat_p1 = (const float*)d_in[0];
    const float* feat_p2 = (const float*)d_in[1];
    const float* feat_n  = (const float*)d_in[2];
    const float* w_p1    = (const float*)d_in[3];
    const float* w_p2    = (const float*)d_in[4];
    const float* w_n     = (const float*)d_in[5];
    const float* W_enc   = (const float*)d_in[6];
    const float* b_enc   = (const float*)d_in[7];
    const float* W_dec   = (const float*)d_in[8];
    const float* b_dec   = (const float*)d_in[9];
    const float* W_bil   = (const float*)d_in[10];
    const float* b_bil   = (const float*)d_in[11];
    const int* src_p1 = (const int*)d_in[12];
    const int* dst_p1 = (const int*)d_in[13];
    const int* src_p2 = (const int*)d_in[14];
    const int* dst_p2 = (const int*)d_in[15];
    const int* src_n  = (const int*)d_in[16];
    const int* dst_n  = (const int*)d_in[17];
    float* out = (float*)d_out;

    cudaFuncSetAttribute(gemm_mma, cudaFuncAttributeMaxDynamicSharedMemorySize, GEMM_SMEM);
    cudaFuncSetAttribute(graph_kernel, cudaFuncAttributeMaxDynamicSharedMemorySize, GK_SMEM);

    prep_W<<<38, 256>>>(W_enc, W_dec);
    gemm_mma<<<3072, 256, GEMM_SMEM>>>(feat_p1, feat_p2, feat_n);

    graph_kernel<<<Bsz / 8, 256, GK_SMEM>>>(
        w_p1, w_p2, w_n, b_enc, W_bil, b_bil,
        src_p1, dst_p1, src_p2, dst_p2, src_n, dst_n);

    dec_err<<<256, 128>>>(feat_p1, feat_p2, b_dec);
    fin_scores<<<32, 256>>>(out);
}

// round 16
// speedup vs baseline: 1.3854x; 1.0171x over previous
#include <cuda_runtime.h>
#include <cuda_bf16.h>
#include <math.h>
#include <stdint.h>

#define Bsz 8192
#define Knod 16
#define Eedg 64
#define FIN 300
#define FOUT 64
#define ALPHA 1.0f
#define BETA 0.6f

static __device__ float g_Y[(size_t)3 * Bsz * Knod * FOUT];   // ~100 MB scratch
static __device__ uint4 g_Wfrag[4864];     // encoder B frags: hi [0,2432), lo [2432,4864)
static __device__ uint4 g_WdF[4864];       // decoder B frags: hi [0,2432), lo [2432,4864)
static __device__ float g_contr[Bsz];
static __device__ float g_part[1024 * 4];

// ---------------- helpers ----------------
__device__ __forceinline__ uint32_t pk_bf2(float x, float y) {
    __nv_bfloat162 t = __floats2bfloat162_rn(x, y);   // x in low 16 bits
    return *(uint32_t*)&t;
}
__device__ __forceinline__ float low_bf(uint32_t h)  { return __uint_as_float(h << 16); }
__device__ __forceinline__ float high_bf(uint32_t h) { return __uint_as_float(h & 0xffff0000u); }

__device__ __forceinline__ void mma16816(float* c, uint32_t a0, uint32_t a1, uint32_t a2, uint32_t a3,
                                         uint32_t b0, uint32_t b1) {
    asm volatile(
        "mma.sync.aligned.m16n8k16.row.col.f32.bf16.bf16.f32 "
        "{%0,%1,%2,%3}, {%4,%5,%6,%7}, {%8,%9}, {%0,%1,%2,%3};"
        : "+f"(c[0]), "+f"(c[1]), "+f"(c[2]), "+f"(c[3])
        : "r"(a0), "r"(a1), "r"(a2), "r"(a3), "r"(b0), "r"(b1));
}
__device__ __forceinline__ float wred(float v) {
    v += __shfl_xor_sync(0xffffffffu, v, 16);
    v += __shfl_xor_sync(0xffffffffu, v, 8);
    v += __shfl_xor_sync(0xffffffffu, v, 4);
    v += __shfl_xor_sync(0xffffffffu, v, 2);
    v += __shfl_xor_sync(0xffffffffu, v, 1);
    return v;
}
__device__ __forceinline__ float bsum256(float v, float* sR) {
    int tid = threadIdx.x;
    sR[tid] = v;
    __syncthreads();
#pragma unroll
    for (int s = 128; s > 0; s >>= 1) {
        if (tid < s) sR[tid] += sR[tid + s];
        __syncthreads();
    }
    float r = sR[0];
    __syncthreads();
    return r;
}

// ===========================================================================
// Kernel 0: precompute W_enc + W_dec fragments (bf16 hi/lo, HMMA B layout)
// ===========================================================================
__global__ void prep_W(const float* __restrict__ W_enc, const float* __restrict__ W_dec) {
    int idx = blockIdx.x * blockDim.x + threadIdx.x;
    if (idx < 4864) {
        int lane = idx & 31, nt = (idx >> 5) & 7, kt = idx >> 8;
        int tig = lane & 3, grp = lane >> 2;
        int n = nt * 8 + grp;
        int k0 = kt * 16 + 2 * tig;
        float e0 = __ldg(&W_enc[k0 * 64 + n]);
        float e1 = __ldg(&W_enc[(k0 + 1) * 64 + n]);
        float e2 = (k0 + 8 < FIN) ? __ldg(&W_enc[(k0 + 8) * 64 + n]) : 0.f;
        float e3 = (k0 + 9 < FIN) ? __ldg(&W_enc[(k0 + 9) * 64 + n]) : 0.f;
        uint32_t b0h = pk_bf2(e0, e1), b1h = pk_bf2(e2, e3);
        uint32_t b0l = pk_bf2(e0 - low_bf(b0h), e1 - high_bf(b0h));
        uint32_t b1l = pk_bf2(e2 - low_bf(b1h), e3 - high_bf(b1h));
        uint32_t* gw = (uint32_t*)g_Wfrag;
        int base = (((kt * 4) + (nt >> 1)) * 32 + lane) * 4 + (nt & 1) * 2;
        gw[base] = b0h;  gw[base + 1] = b1h;
        gw[9728 + base] = b0l;  gw[9728 + base + 1] = b1l;
    } else {
        int i2 = idx - 4864;
        if (i2 >= 4864) return;
        int lane = i2 & 31, kt = (i2 >> 5) & 3, nt = i2 >> 7;
        int tig = lane & 3, grp = lane >> 2;
        int n = nt * 8 + grp;
        int k0 = kt * 16 + 2 * tig;
        float e0 = 0.f, e1 = 0.f, e2 = 0.f, e3 = 0.f;
        if (n < FIN) {
            e0 = __ldg(&W_dec[k0 * FIN + n]);
            e1 = __ldg(&W_dec[(k0 + 1) * FIN + n]);
            e2 = __ldg(&W_dec[(k0 + 8) * FIN + n]);
            e3 = __ldg(&W_dec[(k0 + 9) * FIN + n]);
        }
        uint32_t b0h = pk_bf2(e0, e1), b1h = pk_bf2(e2, e3);
        uint32_t b0l = pk_bf2(e0 - low_bf(b0h), e1 - high_bf(b0h));
        uint32_t b1l = pk_bf2(e2 - low_bf(b1h), e3 - high_bf(b1h));
        uint32_t* gw = (uint32_t*)g_WdF;
        int base = (((nt >> 1) * 4 + kt) * 32 + lane) * 4 + (nt & 1) * 2;
        gw[base] = b0h;  gw[base + 1] = b1h;
        gw[9728 + base] = b0l;  gw[9728 + base + 1] = b1l;
    }
}

// ===========================================================================
// Kernel 1: HMMA split-bf16 GEMM  Y = feat @ W_enc  (depth-1 prefetch,
// smem-staged coalesced epilogue) — R15 known-good, unchanged.
// ===========================================================================
#define GEMM_SMEM (4864 * 16)

__global__ void __launch_bounds__(256, 2) gemm_mma(
    const float* __restrict__ f1, const float* __restrict__ f2,
    const float* __restrict__ fn)
{
    extern __shared__ uint4 sB[];    // hi [0,2432), lo [2432,4864); reused as sY after k-loop
    const int tid = threadIdx.x;
    const int w = tid >> 5, lane = tid & 31;
    const int grp = lane >> 2, tig = lane & 3;

#pragma unroll
    for (int u = 0; u < 19; u++) sB[tid + 256 * u] = g_Wfrag[tid + 256 * u];
    __syncthreads();

    const int s = blockIdx.x >> 10, blk = blockIdx.x & 1023;
    const float* A = ((s == 0) ? f1 : (s == 1) ? f2 : fn) + (size_t)blk * 128 * FIN;
    const float* Ar0 = A + (size_t)(w * 16 + grp) * FIN;
    const float* Ar1 = Ar0 + 8 * FIN;

    float acc[8][4];
#pragma unroll
    for (int nt = 0; nt < 8; nt++)
#pragma unroll
        for (int q = 0; q < 4; q++) acc[nt][q] = 0.f;

    float2 v00, v10, v01, v11;
    {
        const int c0 = 2 * tig, c1 = c0 + 8;
        v00 = *(const float2*)(Ar0 + c0);
        v10 = *(const float2*)(Ar1 + c0);
        v01 = *(const float2*)(Ar0 + c1);
        v11 = *(const float2*)(Ar1 + c1);
    }

#pragma unroll 1
    for (int kt = 0; kt < 19; kt++) {
        uint32_t ah0 = pk_bf2(v00.x, v00.y);
        uint32_t ah1 = pk_bf2(v10.x, v10.y);
        uint32_t ah2 = pk_bf2(v01.x, v01.y);
        uint32_t ah3 = pk_bf2(v11.x, v11.y);
        uint32_t al0 = pk_bf2(v00.x - low_bf(ah0), v00.y - high_bf(ah0));
        uint32_t al1 = pk_bf2(v10.x - low_bf(ah1), v10.y - high_bf(ah1));
        uint32_t al2 = pk_bf2(v01.x - low_bf(ah2), v01.y - high_bf(ah2));
        uint32_t al3 = pk_bf2(v11.x - low_bf(ah3), v11.y - high_bf(ah3));

        float2 t00, t10, t01, t11;
        if (kt < 18) {
            const int c0 = (kt + 1) * 16 + 2 * tig;
            const int c1 = c0 + 8;
            t00 = *(const float2*)(Ar0 + c0);
            t10 = *(const float2*)(Ar1 + c0);
            t01 = (c1 < FIN) ? *(const float2*)(Ar0 + c1) : make_float2(0.f, 0.f);
            t11 = (c1 < FIN) ? *(const float2*)(Ar1 + c1) : make_float2(0.f, 0.f);
        } else {
            t00 = v00; t10 = v10; t01 = v01; t11 = v11;
        }

#pragma unroll
        for (int p = 0; p < 4; p++) {
            uint4 H = sB[(kt * 4 + p) * 32 + lane];
            uint4 L = sB[2432 + (kt * 4 + p) * 32 + lane];
            mma16816(acc[2 * p],     ah0, ah1, ah2, ah3, H.x, H.y);
            mma16816(acc[2 * p + 1], ah0, ah1, ah2, ah3, H.z, H.w);
            mma16816(acc[2 * p],     ah0, ah1, ah2, ah3, L.x, L.y);
            mma16816(acc[2 * p + 1], ah0, ah1, ah2, ah3, L.z, L.w);
            mma16816(acc[2 * p],     al0, al1, al2, al3, H.x, H.y);
            mma16816(acc[2 * p + 1], al0, al1, al2, al3, H.z, H.w);
        }
        v00 = t00; v10 = t10; v01 = t01; v11 = t11;
    }

    __syncthreads();
    float* sY = (float*)sB;               // [128][68] padded rows
#pragma unroll
    for (int nt = 0; nt < 8; nt++) {
        int col = nt * 8 + 2 * tig;
        *(float2*)&sY[(w * 16 + grp) * 68 + col]     = make_float2(acc[nt][0], acc[nt][1]);
        *(float2*)&sY[(w * 16 + grp + 8) * 68 + col] = make_float2(acc[nt][2], acc[nt][3]);
    }
    __syncthreads();
    float* Yc = g_Y + ((size_t)s * (Bsz * Knod) + (size_t)blk * 128) * 64;
#pragma unroll
    for (int u = 0; u < 8; u++) {
        int j = tid + 256 * u;
        int row = j >> 4, c4 = (j & 15) * 4;
        *(float4*)&Yc[row * 64 + c4] = *(const float4*)&sY[row * 68 + c4];
    }
}

// ===========================================================================
// Kernel 2: warp-per-graph encoder/SpMM/disc + FUSED HMMA decoder + error.
// ===========================================================================
#define GSTR 2880
#define OY    0
#define OAGG  1024
#define OSRC  2048
#define ODST  2112
#define OWE   2176
#define OA    2240
#define OPOOL 2368
#define OSCAL 2688
#define ODEG  2696
#define OND   2712
#define OV    2752          // V rows: [s][64], s = dec index
#define SWB_OFF (8 * GSTR)                 // 23040, 64x65 floats
#define SLT_OFF (SWB_OFF + 4160)           // 27200, 16 floats
#define GK_SMEM ((SLT_OFF + 16) * 4)       // 108864 B

__global__ void __launch_bounds__(256, 2) graph_kernel(
    const float* __restrict__ fp1, const float* __restrict__ fp2,
    const float* __restrict__ w_p1, const float* __restrict__ w_p2,
    const float* __restrict__ w_n,
    const float* __restrict__ b_enc, const float* __restrict__ W_bil,
    const float* __restrict__ b_bil, const float* __restrict__ b_dec,
    const int* __restrict__ sp1, const int* __restrict__ dp1,
    const int* __restrict__ sp2, const int* __restrict__ dp2,
    const int* __restrict__ spn, const int* __restrict__ dpn)
{
    extern __shared__ float sm[];
    float* sWb = sm + SWB_OFF;
    float* sLT = sm + SLT_OFF;
    const int tid = threadIdx.x, lane = tid & 31, g = tid >> 5;
    const int b = blockIdx.x * 8 + g;
    float* G = sm + g * GSTR;
    int* Gsrc = (int*)(G + OSRC);
    int* Gdst = (int*)(G + ODST);
    float* Gwe = G + OWE;

    for (int j = tid; j < 4096; j += 256)
        sWb[(j >> 6) * 65 + (j & 63)] = __ldg(&W_bil[j]);
    __syncthreads();

    const float2 be = *(const float2*)&b_enc[2 * lane];

    const int* srcs[3] = { sp1 + (long)b * Eedg, sp2 + (long)b * Eedg, spn + (long)b * Eedg };
    const int* dsts[3] = { dp1 + (long)b * Eedg, dp2 + (long)b * Eedg, dpn + (long)b * Eedg };
    const float* wgts[3] = { w_p1 + (long)b * Eedg, w_p2 + (long)b * Eedg, w_n + (long)b * Eedg };

    for (int s = 0; s < 3; s++) {
        Gsrc[lane] = __ldg(&srcs[s][lane]);  Gsrc[lane + 32] = __ldg(&srcs[s][lane + 32]);
        Gdst[lane] = __ldg(&dsts[s][lane]);  Gdst[lane + 32] = __ldg(&dsts[s][lane + 32]);
        Gwe[lane]  = __ldg(&wgts[s][lane]);  Gwe[lane + 32]  = __ldg(&wgts[s][lane + 32]);
        const float4* Yf4 = (const float4*)(g_Y + ((size_t)s * (Bsz * Knod) + (size_t)b * Knod) * 64);
#pragma unroll
        for (int u = 0; u < 8; u++)
            *(float4*)&G[OY + 4 * (lane + 32 * u)] = __ldg(&Yf4[lane + 32 * u]);
#pragma unroll
        for (int k = 0; k < Knod; k++)
            *(float2*)&G[OAGG + k * 64 + 2 * lane] = make_float2(0.f, 0.f);
        __syncwarp();

        for (int e = 0; e < Eedg; e++) {
            int se = Gsrc[e];
            if (se != 0) {
                int de = Gdst[e]; float w = Gwe[e];
                float2 y = *(const float2*)&G[OY + se * 64 + 2 * lane];
                float2* ap = (float2*)&G[OAGG + de * 64 + 2 * lane];
                float2 a = *ap;
                a.x = fmaf(w, y.x, a.x); a.y = fmaf(w, y.y, a.y);
                *ap = a;
            }
        }

        float px = 0.f, py = 0.f;
        if (s < 2) {
            float2 h2[Knod];
            float ssq[Knod];
#pragma unroll
            for (int k = 0; k < Knod; k++) {
                float2 v = *(const float2*)&G[OAGG + k * 64 + 2 * lane];
                v.x = fmaxf(v.x + be.x, 0.f); v.y = fmaxf(v.y + be.y, 0.f);
                px += v.x; py += v.y;
                h2[k] = v;
                ssq[k] = v.x * v.x + v.y * v.y;
            }
#pragma unroll
            for (int st = 16; st > 0; st >>= 1)
#pragma unroll
                for (int k = 0; k < Knod; k++)
                    ssq[k] += __shfl_xor_sync(0xffffffffu, ssq[k], st);
#pragma unroll
            for (int k = 0; k < Knod; k++) {
                float inv = 1.f / fmaxf(sqrtf(ssq[k]), 1e-12f);
                float2 v = h2[k];
                v.x *= inv; v.y *= inv;
                *(float2*)&G[OAGG + k * 64 + 2 * lane] = v;
            }
        } else {
#pragma unroll
            for (int k = 0; k < Knod; k++) {
                float2 v = *(const float2*)&G[OAGG + k * 64 + 2 * lane];
                px += fmaxf(v.x + be.x, 0.f);
                py += fmaxf(v.y + be.y, 0.f);
            }
        }
        px *= (1.f / 16.f); py *= (1.f / 16.f);
        float pn = wred(px * px + py * py);
        float pinv = 1.f / fmaxf(sqrtf(pn), 1e-12f);
        G[OPOOL + s * 64 + 2 * lane]     = px * pinv;
        G[OPOOL + s * 64 + 2 * lane + 1] = py * pinv;

        if (s < 2) {
            float2 av = *(const float2*)&G[OY + 2 * lane];
            av.x = fmaxf(av.x + be.x, 0.f); av.y = fmaxf(av.y + be.y, 0.f);
            float an = wred(av.x * av.x + av.y * av.y);
            float ainv = 1.f / fmaxf(sqrtf(an), 1e-12f);
            G[OA + s * 64 + 2 * lane]     = av.x * ainv;
            G[OA + s * 64 + 2 * lane + 1] = av.y * ainv;

            {
                const int target = lane & 15;
                const int* arr = (lane < 16) ? Gsrc : Gdst;
                int c = 0;
                for (int e = 0; e < Eedg; e++) c += (arr[e] == target);
                if (lane < 16) G[ODEG + lane] = (float)c;
                if (lane == 16) G[OND + s] = rsqrtf(fmaxf((float)c, 1.f));
            }
            __syncwarp();

            float vx = 0.f, vy = 0.f;
            for (int e = 0; e < Eedg; e++) {
                if (Gdst[e] == 0) {
                    int se = Gsrc[e];
                    float rs = rsqrtf(fmaxf(G[ODEG + se], 1.f)) * Gwe[e];
                    float2 h2v = *(const float2*)&G[OAGG + se * 64 + 2 * lane];
                    vx = fmaf(rs, h2v.x, vx);
                    vy = fmaf(rs, h2v.y, vy);
                }
            }
            *(float2*)&G[OV + s * 64 + 2 * lane] = make_float2(vx, vy);
        }
        __syncwarp();
    }

    // discriminators
    {
        const float bb = __ldg(b_bil);
        for (int t = 0; t < 2; t++) {
            float u0 = 0.f, u1 = 0.f;
            const float* wr0 = sWb + lane * 65;
            const float* wr1 = sWb + (lane + 32) * 65;
#pragma unroll 8
            for (int k = 0; k < 64; k++) {
                float ak = G[OA + t * 64 + k];
                u0 = fmaf(wr0[k], ak, u0);
                u1 = fmaf(wr1[k], ak, u1);
            }
            float dp = wred(G[OPOOL + t * 64 + lane] * u0 + G[OPOOL + t * 64 + lane + 32] * u1);
            float dn = wred(G[OPOOL + 128 + lane] * u0 + G[OPOOL + 128 + lane + 32] * u1);
            if (lane == 0) {
                G[OSCAL + t]     = 1.f / (1.f + expf(-(dp + bb)));
                G[OSCAL + 2 + t] = 1.f / (1.f + expf(-(dn + bb)));
            }
        }
    }
    __syncwarp();

    if (lane == 0) {
        float ps1 = G[OSCAL + 0], ps2 = G[OSCAL + 1];
        float ns1 = G[OSCAL + 2], ns2 = G[OSCAL + 3];
        sLT[g]     = logf(ps1) + logf(1.f - ns1);
        sLT[8 + g] = logf(ps2) + logf(1.f - ns2);
        g_contr[b] = (ns1 - ps1 + 1.f) * 0.5f + (ns2 - ps2 + 1.f) * 0.5f;
    }

    // ======== fused decoder: rows r = 2*gslot + s, 16 rows per CTA ========
    __syncthreads();   // V, nd, sLT visible; sWb reads done -> reuse as sDec
    float* sDec = sWb; // [4][16][3]

    if (g < 4) {
        const int grp = lane >> 2, tig = lane & 3;
        // A fragments from smem V (row r: gslot = r>>1, s = r&1)
        uint32_t ah[4][4], al[4][4];
#pragma unroll
        for (int kt = 0; kt < 4; kt++) {
            const int k0 = kt * 16 + 2 * tig;
            const float* V0 = sm + (grp >> 1) * GSTR + OV + (grp & 1) * 64;
            const float* V1 = sm + ((grp >> 1) + 4) * GSTR + OV + (grp & 1) * 64;
            float2 x00 = *(const float2*)(V0 + k0);
            float2 x10 = *(const float2*)(V1 + k0);
            float2 x01 = *(const float2*)(V0 + k0 + 8);
            float2 x11 = *(const float2*)(V1 + k0 + 8);
            ah[kt][0] = pk_bf2(x00.x, x00.y);
            ah[kt][1] = pk_bf2(x10.x, x10.y);
            ah[kt][2] = pk_bf2(x01.x, x01.y);
            ah[kt][3] = pk_bf2(x11.x, x11.y);
            al[kt][0] = pk_bf2(x00.x - low_bf(ah[kt][0]), x00.y - high_bf(ah[kt][0]));
            al[kt][1] = pk_bf2(x10.x - low_bf(ah[kt][1]), x10.y - high_bf(ah[kt][1]));
            al[kt][2] = pk_bf2(x01.x - low_bf(ah[kt][2]), x01.y - high_bf(ah[kt][2]));
            al[kt][3] = pk_bf2(x11.x - low_bf(ah[kt][3]), x11.y - high_bf(ah[kt][3]));
        }
        const float nd0 = sm[(grp >> 1) * GSTR + OND + (grp & 1)];
        const float nd1 = sm[((grp >> 1) + 4) * GSTR + OND + (grp & 1)];
        const float* ori0 = ((grp & 1) ? fp2 : fp1) +
            (size_t)(blockIdx.x * 8 + (grp >> 1)) * (Knod * FIN);
        const float* ori1 = ((grp & 1) ? fp2 : fp1) +
            (size_t)(blockIdx.x * 8 + (grp >> 1) + 4) * (Knod * FIN);

        float shh0 = 0.f, sho0 = 0.f, soo0 = 0.f;
        float shh1 = 0.f, sho1 = 0.f, soo1 = 0.f;

#pragma unroll 1
        for (int ntp = g; ntp < 19; ntp += 4) {
            float acc0[4] = {0.f, 0.f, 0.f, 0.f};
            float acc1[4] = {0.f, 0.f, 0.f, 0.f};
#pragma unroll
            for (int kt = 0; kt < 4; kt++) {
                uint4 H = __ldg(&g_WdF[(ntp * 4 + kt) * 32 + lane]);
                uint4 L = __ldg(&g_WdF[2432 + (ntp * 4 + kt) * 32 + lane]);
                mma16816(acc0, ah[kt][0], ah[kt][1], ah[kt][2], ah[kt][3], H.x, H.y);
                mma16816(acc1, ah[kt][0], ah[kt][1], ah[kt][2], ah[kt][3], H.z, H.w);
                mma16816(acc0, ah[kt][0], ah[kt][1], ah[kt][2], ah[kt][3], L.x, L.y);
                mma16816(acc1, ah[kt][0], ah[kt][1], ah[kt][2], ah[kt][3], L.z, L.w);
                mma16816(acc0, al[kt][0], al[kt][1], al[kt][2], al[kt][3], H.x, H.y);
                mma16816(acc1, al[kt][0], al[kt][1], al[kt][2], al[kt][3], H.z, H.w);
            }
#pragma unroll
            for (int half = 0; half < 2; half++) {
                const float* accP = half ? acc1 : acc0;
                const int col = ntp * 16 + half * 8 + 2 * tig;
                if (col < FIN) {
                    float2 bd = *(const float2*)&b_dec[col];
                    float h00 = fmaxf(accP[0] * nd0 + bd.x, 0.f);
                    float h01 = fmaxf(accP[1] * nd0 + bd.y, 0.f);
                    float h10 = fmaxf(accP[2] * nd1 + bd.x, 0.f);
                    float h11 = fmaxf(accP[3] * nd1 + bd.y, 0.f);
                    float2 o0 = *(const float2*)(ori0 + col);
                    float2 o1 = *(const float2*)(ori1 + col);
                    shh0 += h00 * h00 + h01 * h01;
                    sho0 += h00 * o0.x + h01 * o0.y;
                    soo0 += o0.x * o0.x + o0.y * o0.y;
                    shh1 += h10 * h10 + h11 * h11;
                    sho1 += h10 * o1.x + h11 * o1.y;
                    soo1 += o1.x * o1.x + o1.y * o1.y;
                }
            }
        }

#pragma unroll
        for (int st = 1; st < 4; st <<= 1) {
            shh0 += __shfl_xor_sync(0xffffffffu, shh0, st);
            sho0 += __shfl_xor_sync(0xffffffffu, sho0, st);
            soo0 += __shfl_xor_sync(0xffffffffu, soo0, st);
            shh1 += __shfl_xor_sync(0xffffffffu, shh1, st);
            sho1 += __shfl_xor_sync(0xffffffffu, sho1, st);
            soo1 += __shfl_xor_sync(0xffffffffu, soo1, st);
        }
        if (tig == 0) {
            // row r0 = grp (0..7), r1 = grp+8
            sDec[(g * 16 + grp) * 3 + 0] = shh0;
            sDec[(g * 16 + grp) * 3 + 1] = sho0;
            sDec[(g * 16 + grp) * 3 + 2] = soo0;
            sDec[(g * 16 + grp + 8) * 3 + 0] = shh1;
            sDec[(g * 16 + grp + 8) * 3 + 1] = sho1;
            sDec[(g * 16 + grp + 8) * 3 + 2] = soo1;
        }
    }
    __syncthreads();

    if (g == 0) {
        float E0c = 0.f, E1c = 0.f, L1c = 0.f, L2c = 0.f;
        if (lane < 16) {
            const int r = lane;
            float shh = sDec[(r) * 3] + sDec[(16 + r) * 3] + sDec[(32 + r) * 3] + sDec[(48 + r) * 3];
            float sho = sDec[(r) * 3 + 1] + sDec[(16 + r) * 3 + 1] + sDec[(32 + r) * 3 + 1] + sDec[(48 + r) * 3 + 1];
            float soo = sDec[(r) * 3 + 2] + sDec[(16 + r) * 3 + 2] + sDec[(32 + r) * 3 + 2] + sDec[(48 + r) * 3 + 2];
            float inv = 1.f / fmaxf(sqrtf(shh), 1e-12f);
            float e = shh * inv * inv - 2.f * inv * sho + soo;
            if (r & 1) E1c = e; else E0c = e;
            if (lane < 8) L1c = sLT[lane];
            else L2c = sLT[lane];
        }
#pragma unroll
        for (int st = 1; st < 32; st <<= 1) {
            E0c += __shfl_xor_sync(0xffffffffu, E0c, st);
            E1c += __shfl_xor_sync(0xffffffffu, E1c, st);
            L1c += __shfl_xor_sync(0xffffffffu, L1c, st);
            L2c += __shfl_xor_sync(0xffffffffu, L2c, st);
        }
        if (lane == 0) {
            g_part[blockIdx.x * 4 + 0] = E0c;
            g_part[blockIdx.x * 4 + 1] = E1c;
            g_part[blockIdx.x * 4 + 2] = L1c;
            g_part[blockIdx.x * 4 + 3] = L2c;
        }
    }
}

// ===========================================================================
// Kernel 3: fused finalize + scores. 32 CTAs x 256; reduce 1024x4 partials.
// ===========================================================================
__global__ void __launch_bounds__(256) fin_scores(float* out) {
    __shared__ float sR[256];
    const int tid = threadIdx.x;
    float a = 0.f, c = 0.f, m1 = 0.f, m2 = 0.f;
#pragma unroll
    for (int j = 0; j < 4; j++) {
        int p = tid + 256 * j;
        a  += g_part[p * 4 + 0];
        c  += g_part[p * 4 + 1];
        m1 += g_part[p * 4 + 2];
        m2 += g_part[p * 4 + 3];
    }
    float Ssq1 = bsum256(a, sR);
    float Ssq2 = bsum256(c, sR);
    float M1 = bsum256(m1, sR);
    float M2 = bsum256(m2, sR);

    if (blockIdx.x == 0 && tid == 0) {
        float L_con = -(M1 / (float)Bsz + M2 / (float)Bsz) * 0.25f;
        float L_gen = (Ssq1 + Ssq2) / (2.f * (float)Bsz * (float)FIN);
        out[0] = ALPHA * L_con + BETA * L_gen;
    }
    float gen = (sqrtf(Ssq1) + sqrtf(Ssq2)) / (2.f * sqrtf((float)FIN));
    int i = blockIdx.x * 256 + tid;
    out[1 + i] = ALPHA * g_contr[i] + BETA * gen;
}

// ===========================================================================
extern "C" void kernel_launch(void* const* d_in, const int* in_sizes, int n_in,
                              void* d_out, int out_size) {
    const float* feat_p1 = (const float*)d_in[0];
    const float* feat_p2 = (const float*)d_in[1];
    const float* feat_n  = (const float*)d_in[2];
    const float* w_p1    = (const float*)d_in[3];
    const float* w_p2    = (const float*)d_in[4];
    const float* w_n     = (const float*)d_in[5];
    const float* W_enc   = (const float*)d_in[6];
    const float* b_enc   = (const float*)d_in[7];
    const float* W_dec   = (const float*)d_in[8];
    const float* b_dec   = (const float*)d_in[9];
    const float* W_bil   = (const float*)d_in[10];
    const float* b_bil   = (const float*)d_in[11];
    const int* src_p1 = (const int*)d_in[12];
    const int* dst_p1 = (const int*)d_in[13];
    const int* src_p2 = (const int*)d_in[14];
    const int* dst_p2 = (const int*)d_in[15];
    const int* src_n  = (const int*)d_in[16];
    const int* dst_n  = (const int*)d_in[17];
    float* out = (float*)d_out;

    cudaFuncSetAttribute(gemm_mma, cudaFuncAttributeMaxDynamicSharedMemorySize, GEMM_SMEM);
    cudaFuncSetAttribute(graph_kernel, cudaFuncAttributeMaxDynamicSharedMemorySize, GK_SMEM);

    prep_W<<<38, 256>>>(W_enc, W_dec);
    gemm_mma<<<3072, 256, GEMM_SMEM>>>(feat_p1, feat_p2, feat_n);

    graph_kernel<<<Bsz / 8, 256, GK_SMEM>>>(
        feat_p1, feat_p2, w_p1, w_p2, w_n,
        b_enc, W_bil, b_bil, b_dec,
        src_p1, dst_p1, src_p2, dst_p2, src_n, dst_n);

    fin_scores<<<32, 256>>>(out);
}